// round 2
// baseline (speedup 1.0000x reference)
#include <cuda_runtime.h>
#include <cstdint>

#define NN   50000
#define NE   800000
#define FIN  128
#define FHID 256
#define FOUT 128

// -------- scratch (static device arrays; no allocation allowed) ----------
__device__ int   g_outdeg[NN];
__device__ int   g_indeg[NN];
__device__ int   g_cur[NN];
__device__ int   g_off[NN + 1];
__device__ int   g_adj[NE];
__device__ int   g_bsum[256];
__device__ int   g_bbase[256];
__device__ float g_oisq[NN];
__device__ float g_iisq[NN];
__device__ float g_m1[(size_t)NN * FIN];
__device__ float g_h1[(size_t)NN * FHID];
__device__ float g_m2[(size_t)NN * FHID];

#define SCAN_NB ((NN + 255) / 256)   // 196

// -------- setup kernels --------------------------------------------------
__global__ void k_init() {
    int i = blockIdx.x * blockDim.x + threadIdx.x;
    if (i < NN) {
        g_outdeg[i] = 1;   // self-loop
        g_indeg[i]  = 1;   // self-loop
        g_cur[i]    = 0;
    }
    if (i == 0) g_off[NN] = NE;
}

__global__ void k_count(const int* __restrict__ ei) {
    int e = blockIdx.x * blockDim.x + threadIdx.x;
    if (e < NE) {
        atomicAdd(&g_outdeg[ei[e]], 1);        // src
        atomicAdd(&g_indeg[ei[NE + e]], 1);    // dst
    }
}

__global__ void k_isqrt() {
    int i = blockIdx.x * blockDim.x + threadIdx.x;
    if (i < NN) {
        g_oisq[i] = rsqrtf((float)g_outdeg[i]);
        g_iisq[i] = rsqrtf((float)g_indeg[i]);
    }
}

// -------- 3-kernel exclusive scan of (indeg-1) --------------------------
__global__ void k_scan1() {
    __shared__ int sh[256];
    int tid = threadIdx.x;
    int idx = blockIdx.x * 256 + tid;
    int v = (idx < NN) ? (g_indeg[idx] - 1) : 0;
    sh[tid] = v;
    __syncthreads();
    for (int ofs = 1; ofs < 256; ofs <<= 1) {
        int t = (tid >= ofs) ? sh[tid - ofs] : 0;
        __syncthreads();
        sh[tid] += t;
        __syncthreads();
    }
    if (idx < NN) g_off[idx] = sh[tid] - v;          // local exclusive
    if (tid == 255) g_bsum[blockIdx.x] = sh[255];    // block total
}

__global__ void k_scan2() {
    __shared__ int sh[256];
    int tid = threadIdx.x;
    int v = (tid < SCAN_NB) ? g_bsum[tid] : 0;
    sh[tid] = v;
    __syncthreads();
    for (int ofs = 1; ofs < 256; ofs <<= 1) {
        int t = (tid >= ofs) ? sh[tid - ofs] : 0;
        __syncthreads();
        sh[tid] += t;
        __syncthreads();
    }
    g_bbase[tid] = sh[tid] - v;                      // exclusive base
}

__global__ void k_scan3() {
    int idx = blockIdx.x * 256 + threadIdx.x;
    if (idx < NN) g_off[idx] += g_bbase[blockIdx.x];
}

__global__ void k_fill(const int* __restrict__ ei) {
    int e = blockIdx.x * blockDim.x + threadIdx.x;
    if (e < NE) {
        int s = ei[e];
        int d = ei[NE + e];
        int p = g_off[d] + atomicAdd(&g_cur[d], 1);
        g_adj[p] = s;
    }
}

// -------- aggregation: one warp per node, CSR gather-sum ------------------
template <int F>
__global__ void agg_kernel(const float* __restrict__ X, float* __restrict__ Out) {
    int w    = (blockIdx.x * blockDim.x + threadIdx.x) >> 5;
    int lane = threadIdx.x & 31;
    if (w >= NN) return;
    constexpr int V = F / 128;   // float4 chunks per lane

    float so = g_oisq[w];
    float4 acc[V];
    const float4* xr = (const float4*)(X + (size_t)w * F);
#pragma unroll
    for (int i = 0; i < V; i++) {
        float4 t = __ldg(&xr[i * 32 + lane]);
        acc[i].x = t.x * so; acc[i].y = t.y * so;
        acc[i].z = t.z * so; acc[i].w = t.w * so;
    }
    int j0 = g_off[w];
    int j1 = g_off[w + 1];
    for (int j = j0; j < j1; ++j) {
        int u   = g_adj[j];
        float su = g_oisq[u];
        const float4* ur = (const float4*)(X + (size_t)u * F);
#pragma unroll
        for (int i = 0; i < V; i++) {
            float4 t = __ldg(&ur[i * 32 + lane]);
            acc[i].x += t.x * su; acc[i].y += t.y * su;
            acc[i].z += t.z * su; acc[i].w += t.w * su;
        }
    }
    float si = g_iisq[w];
    float4* orow = (float4*)(Out + (size_t)w * F);
#pragma unroll
    for (int i = 0; i < V; i++) {
        float4 o;
        o.x = acc[i].x * si; o.y = acc[i].y * si;
        o.z = acc[i].z * si; o.w = acc[i].w * si;
        orow[i * 32 + lane] = o;
    }
}

// -------- fp32 tiled GEMM: C = A[MxK] * B[KxNc] + bias, optional relu -----
// BM=BN=128, BK=8, 256 threads, each thread 8x8
template <bool RELU>
__global__ void gemm_bias(const float* __restrict__ A, const float* __restrict__ B,
                          const float* __restrict__ bias, float* __restrict__ C,
                          int M, int K, int Nc) {
    __shared__ float As[8][128];
    __shared__ float Bs[8][128];
    int tid = threadIdx.x;
    int tx = tid & 15;        // 0..15 -> col group
    int ty = tid >> 4;        // 0..15 -> row group
    int rowTile = blockIdx.y * 128;
    int colTile = blockIdx.x * 128;

    float acc[8][8];
#pragma unroll
    for (int i = 0; i < 8; i++)
#pragma unroll
        for (int j = 0; j < 8; j++) acc[i][j] = 0.f;

    int a_row = tid >> 1;            // 0..127
    int a_col = (tid & 1) * 4;       // 0 or 4
    int b_row = tid >> 5;            // 0..7
    int b_col = (tid & 31) * 4;      // 0..124

    for (int k0 = 0; k0 < K; k0 += 8) {
        float4 av = make_float4(0.f, 0.f, 0.f, 0.f);
        int gr = rowTile + a_row;
        if (gr < M) av = *(const float4*)(A + (size_t)gr * K + k0 + a_col);
        As[a_col + 0][a_row] = av.x;
        As[a_col + 1][a_row] = av.y;
        As[a_col + 2][a_row] = av.z;
        As[a_col + 3][a_row] = av.w;

        float4 bv = *(const float4*)(B + (size_t)(k0 + b_row) * Nc + colTile + b_col);
        *(float4*)(&Bs[b_row][b_col]) = bv;
        __syncthreads();

#pragma unroll
        for (int k = 0; k < 8; k++) {
            float ar[8], br[8];
#pragma unroll
            for (int i = 0; i < 8; i++) ar[i] = As[k][ty * 8 + i];
#pragma unroll
            for (int j = 0; j < 8; j++) br[j] = Bs[k][tx * 8 + j];
#pragma unroll
            for (int i = 0; i < 8; i++)
#pragma unroll
                for (int j = 0; j < 8; j++) acc[i][j] += ar[i] * br[j];
        }
        __syncthreads();
    }

    // epilogue: float4 stores
#pragma unroll
    for (int i = 0; i < 8; i++) {
        int r = rowTile + ty * 8 + i;
        if (r < M) {
#pragma unroll
            for (int j4 = 0; j4 < 2; j4++) {
                int c = colTile + tx * 8 + j4 * 4;
                float4 o;
                o.x = acc[i][j4 * 4 + 0] + __ldg(&bias[c + 0]);
                o.y = acc[i][j4 * 4 + 1] + __ldg(&bias[c + 1]);
                o.z = acc[i][j4 * 4 + 2] + __ldg(&bias[c + 2]);
                o.w = acc[i][j4 * 4 + 3] + __ldg(&bias[c + 3]);
                if (RELU) {
                    o.x = fmaxf(o.x, 0.f); o.y = fmaxf(o.y, 0.f);
                    o.z = fmaxf(o.z, 0.f); o.w = fmaxf(o.w, 0.f);
                }
                *(float4*)(C + (size_t)r * Nc + c) = o;
            }
        }
    }
}

// wrappers that source/sink the __device__ scratch directly (no
// cudaGetSymbolAddress needed in kernel_launch)
__global__ void agg1_entry(const float* __restrict__ X) {
    // forwards to agg logic inline: F=FIN, Out=g_m1
    int w    = (blockIdx.x * blockDim.x + threadIdx.x) >> 5;
    int lane = threadIdx.x & 31;
    if (w >= NN) return;
    constexpr int V = FIN / 128;
    float so = g_oisq[w];
    float4 acc[V];
    const float4* xr = (const float4*)(X + (size_t)w * FIN);
#pragma unroll
    for (int i = 0; i < V; i++) {
        float4 t = __ldg(&xr[i * 32 + lane]);
        acc[i].x = t.x * so; acc[i].y = t.y * so;
        acc[i].z = t.z * so; acc[i].w = t.w * so;
    }
    int j0 = g_off[w], j1 = g_off[w + 1];
    for (int j = j0; j < j1; ++j) {
        int u = g_adj[j];
        float su = g_oisq[u];
        const float4* ur = (const float4*)(X + (size_t)u * FIN);
#pragma unroll
        for (int i = 0; i < V; i++) {
            float4 t = __ldg(&ur[i * 32 + lane]);
            acc[i].x += t.x * su; acc[i].y += t.y * su;
            acc[i].z += t.z * su; acc[i].w += t.w * su;
        }
    }
    float si = g_iisq[w];
    float4* orow = (float4*)(g_m1 + (size_t)w * FIN);
#pragma unroll
    for (int i = 0; i < V; i++) {
        float4 o;
        o.x = acc[i].x * si; o.y = acc[i].y * si;
        o.z = acc[i].z * si; o.w = acc[i].w * si;
        orow[i * 32 + lane] = o;
    }
}

__global__ void agg2_entry() {
    int w    = (blockIdx.x * blockDim.x + threadIdx.x) >> 5;
    int lane = threadIdx.x & 31;
    if (w >= NN) return;
    constexpr int V = FHID / 128;
    const float* X = g_h1;
    float so = g_oisq[w];
    float4 acc[V];
    const float4* xr = (const float4*)(X + (size_t)w * FHID);
#pragma unroll
    for (int i = 0; i < V; i++) {
        float4 t = __ldg(&xr[i * 32 + lane]);
        acc[i].x = t.x * so; acc[i].y = t.y * so;
        acc[i].z = t.z * so; acc[i].w = t.w * so;
    }
    int j0 = g_off[w], j1 = g_off[w + 1];
    for (int j = j0; j < j1; ++j) {
        int u = g_adj[j];
        float su = g_oisq[u];
        const float4* ur = (const float4*)(X + (size_t)u * FHID);
#pragma unroll
        for (int i = 0; i < V; i++) {
            float4 t = __ldg(&ur[i * 32 + lane]);
            acc[i].x += t.x * su; acc[i].y += t.y * su;
            acc[i].z += t.z * su; acc[i].w += t.w * su;
        }
    }
    float si = g_iisq[w];
    float4* orow = (float4*)(g_m2 + (size_t)w * FHID);
#pragma unroll
    for (int i = 0; i < V; i++) {
        float4 o;
        o.x = acc[i].x * si; o.y = acc[i].y * si;
        o.z = acc[i].z * si; o.w = acc[i].w * si;
        orow[i * 32 + lane] = o;
    }
}

// GEMM entries binding scratch buffers as A/C internally
__global__ void gemm1_entry(const float* __restrict__ W1, const float* __restrict__ b1) {
    // C=g_h1 = relu(g_m1 @ W1 + b1), M=NN K=FIN Nc=FHID
    __shared__ float As[8][128];
    __shared__ float Bs[8][128];
    const float* A = g_m1;
    const float* B = W1;
    float* C = g_h1;
    const int K = FIN, Nc = FHID, M = NN;
    int tid = threadIdx.x;
    int tx = tid & 15, ty = tid >> 4;
    int rowTile = blockIdx.y * 128, colTile = blockIdx.x * 128;
    float acc[8][8];
#pragma unroll
    for (int i = 0; i < 8; i++)
#pragma unroll
        for (int j = 0; j < 8; j++) acc[i][j] = 0.f;
    int a_row = tid >> 1, a_col = (tid & 1) * 4;
    int b_row = tid >> 5, b_col = (tid & 31) * 4;
    for (int k0 = 0; k0 < K; k0 += 8) {
        float4 av = make_float4(0.f, 0.f, 0.f, 0.f);
        int gr = rowTile + a_row;
        if (gr < M) av = *(const float4*)(A + (size_t)gr * K + k0 + a_col);
        As[a_col + 0][a_row] = av.x; As[a_col + 1][a_row] = av.y;
        As[a_col + 2][a_row] = av.z; As[a_col + 3][a_row] = av.w;
        float4 bv = *(const float4*)(B + (size_t)(k0 + b_row) * Nc + colTile + b_col);
        *(float4*)(&Bs[b_row][b_col]) = bv;
        __syncthreads();
#pragma unroll
        for (int k = 0; k < 8; k++) {
            float ar[8], br[8];
#pragma unroll
            for (int i = 0; i < 8; i++) ar[i] = As[k][ty * 8 + i];
#pragma unroll
            for (int j = 0; j < 8; j++) br[j] = Bs[k][tx * 8 + j];
#pragma unroll
            for (int i = 0; i < 8; i++)
#pragma unroll
                for (int j = 0; j < 8; j++) acc[i][j] += ar[i] * br[j];
        }
        __syncthreads();
    }
#pragma unroll
    for (int i = 0; i < 8; i++) {
        int r = rowTile + ty * 8 + i;
        if (r < M) {
#pragma unroll
            for (int j4 = 0; j4 < 2; j4++) {
                int c = colTile + tx * 8 + j4 * 4;
                float4 o;
                o.x = fmaxf(acc[i][j4*4+0] + __ldg(&b1[c+0]), 0.f);
                o.y = fmaxf(acc[i][j4*4+1] + __ldg(&b1[c+1]), 0.f);
                o.z = fmaxf(acc[i][j4*4+2] + __ldg(&b1[c+2]), 0.f);
                o.w = fmaxf(acc[i][j4*4+3] + __ldg(&b1[c+3]), 0.f);
                *(float4*)(C + (size_t)r * Nc + c) = o;
            }
        }
    }
}

__global__ void gemm2_entry(const float* __restrict__ W2, const float* __restrict__ b2,
                            float* __restrict__ C) {
    // C=out = g_m2 @ W2 + b2, M=NN K=FHID Nc=FOUT
    __shared__ float As[8][128];
    __shared__ float Bs[8][128];
    const float* A = g_m2;
    const float* B = W2;
    const int K = FHID, Nc = FOUT, M = NN;
    int tid = threadIdx.x;
    int tx = tid & 15, ty = tid >> 4;
    int rowTile = blockIdx.y * 128, colTile = blockIdx.x * 128;
    float acc[8][8];
#pragma unroll
    for (int i = 0; i < 8; i++)
#pragma unroll
        for (int j = 0; j < 8; j++) acc[i][j] = 0.f;
    int a_row = tid >> 1, a_col = (tid & 1) * 4;
    int b_row = tid >> 5, b_col = (tid & 31) * 4;
    for (int k0 = 0; k0 < K; k0 += 8) {
        float4 av = make_float4(0.f, 0.f, 0.f, 0.f);
        int gr = rowTile + a_row;
        if (gr < M) av = *(const float4*)(A + (size_t)gr * K + k0 + a_col);
        As[a_col + 0][a_row] = av.x; As[a_col + 1][a_row] = av.y;
        As[a_col + 2][a_row] = av.z; As[a_col + 3][a_row] = av.w;
        float4 bv = *(const float4*)(B + (size_t)(k0 + b_row) * Nc + colTile + b_col);
        *(float4*)(&Bs[b_row][b_col]) = bv;
        __syncthreads();
#pragma unroll
        for (int k = 0; k < 8; k++) {
            float ar[8], br[8];
#pragma unroll
            for (int i = 0; i < 8; i++) ar[i] = As[k][ty * 8 + i];
#pragma unroll
            for (int j = 0; j < 8; j++) br[j] = Bs[k][tx * 8 + j];
#pragma unroll
            for (int i = 0; i < 8; i++)
#pragma unroll
                for (int j = 0; j < 8; j++) acc[i][j] += ar[i] * br[j];
        }
        __syncthreads();
    }
#pragma unroll
    for (int i = 0; i < 8; i++) {
        int r = rowTile + ty * 8 + i;
        if (r < M) {
#pragma unroll
            for (int j4 = 0; j4 < 2; j4++) {
                int c = colTile + tx * 8 + j4 * 4;
                float4 o;
                o.x = acc[i][j4*4+0] + __ldg(&b2[c+0]);
                o.y = acc[i][j4*4+1] + __ldg(&b2[c+1]);
                o.z = acc[i][j4*4+2] + __ldg(&b2[c+2]);
                o.w = acc[i][j4*4+3] + __ldg(&b2[c+3]);
                *(float4*)(C + (size_t)r * Nc + c) = o;
            }
        }
    }
}

// -------- launcher: pure kernel launches, nothing else --------------------
extern "C" void kernel_launch(void* const* d_in, const int* in_sizes, int n_in,
                              void* d_out, int out_size) {
    const float* x  = (const float*)d_in[0];
    const int*   ei = (const int*)d_in[1];
    const float* W1 = (const float*)d_in[2];
    const float* b1 = (const float*)d_in[3];
    const float* W2 = (const float*)d_in[4];
    const float* b2 = (const float*)d_in[5];
    float* out = (float*)d_out;

    const int TB = 256;
    int gN = (NN + TB - 1) / TB;
    int gE = (NE + TB - 1) / TB;

    k_init<<<gN, TB>>>();
    k_count<<<gE, TB>>>(ei);
    k_isqrt<<<gN, TB>>>();
    k_scan1<<<SCAN_NB, 256>>>();
    k_scan2<<<1, 256>>>();
    k_scan3<<<SCAN_NB, 256>>>();
    k_fill<<<gE, TB>>>(ei);

    int aggBlocks = (NN * 32 + TB - 1) / TB;
    agg1_entry<<<aggBlocks, TB>>>(x);

    dim3 g1((FHID + 127) / 128, (NN + 127) / 128);
    gemm1_entry<<<g1, 256>>>(W1, b1);

    agg2_entry<<<aggBlocks, TB>>>();

    dim3 g2((FOUT + 127) / 128, (NN + 127) / 128);
    gemm2_entry<<<g2, 256>>>(W2, b2, out);
}

// round 4
// speedup vs baseline: 1.2712x; 1.2712x over previous
#include <cuda_runtime.h>
#include <cuda_bf16.h>
#include <cstdint>

#define NN   50000
#define NE   800000
#define FIN  128
#define FHID 256
#define FOUT 128
#define SCAN_NB ((NN + 255) / 256)   // 196

// -------- scratch ---------------------------------------------------------
__device__ int   g_outdeg[NN];
__device__ int   g_indeg[NN];
__device__ int   g_cur[NN];
__device__ int   g_off[NN + 1];
__device__ int   g_adj[NE];
__device__ int   g_bsum[256];
__device__ int   g_bbase[256];
__device__ float g_oisq[NN];
__device__ float g_iisq[NN];
__device__ float g_m1[(size_t)NN * FIN];    // agg(x)         [NN,128]
__device__ float g_h1[(size_t)NN * FHID];   // relu(m1W1+b1)  [NN,256]
__device__ float g_m2[(size_t)NN * FOUT];   // h1@W2          [NN,128]

// ======================= helpers =========================================
__device__ __forceinline__ uint32_t s2u(const void* p) {
    uint32_t a;
    asm("{ .reg .u64 t; cvta.to.shared.u64 t, %1; cvt.u32.u64 %0, t; }"
        : "=r"(a) : "l"(p));
    return a;
}

__device__ __forceinline__ void ldm_x4(uint32_t* r, uint32_t addr) {
    asm volatile("ldmatrix.sync.aligned.m8n8.x4.shared.b16 {%0,%1,%2,%3}, [%4];"
                 : "=r"(r[0]), "=r"(r[1]), "=r"(r[2]), "=r"(r[3]) : "r"(addr));
}
__device__ __forceinline__ void ldm_x2(uint32_t* r, uint32_t addr) {
    asm volatile("ldmatrix.sync.aligned.m8n8.x2.shared.b16 {%0,%1}, [%2];"
                 : "=r"(r[0]), "=r"(r[1]) : "r"(addr));
}
__device__ __forceinline__ void mma_bf16(float* d, const uint32_t* a, const uint32_t* b) {
    asm volatile(
        "mma.sync.aligned.m16n8k16.row.col.f32.bf16.bf16.f32 "
        "{%0,%1,%2,%3}, {%4,%5,%6,%7}, {%8,%9}, {%0,%1,%2,%3};"
        : "+f"(d[0]), "+f"(d[1]), "+f"(d[2]), "+f"(d[3])
        : "r"(a[0]), "r"(a[1]), "r"(a[2]), "r"(a[3]), "r"(b[0]), "r"(b[1]));
}

__device__ __forceinline__ uint32_t pack2(float a, float b) {
    unsigned short ha = __bfloat16_as_ushort(__float2bfloat16(a));
    unsigned short hb = __bfloat16_as_ushort(__float2bfloat16(b));
    return (uint32_t)ha | ((uint32_t)hb << 16);
}

// ======================= setup kernels ===================================
__global__ void k_init() {
    int i = blockIdx.x * blockDim.x + threadIdx.x;
    if (i < NN) { g_outdeg[i] = 1; g_indeg[i] = 1; g_cur[i] = 0; }
    if (i == 0) g_off[NN] = NE;
}
__global__ void k_count(const int* __restrict__ ei) {
    int e = blockIdx.x * blockDim.x + threadIdx.x;
    if (e < NE) {
        atomicAdd(&g_outdeg[ei[e]], 1);
        atomicAdd(&g_indeg[ei[NE + e]], 1);
    }
}
__global__ void k_isqrt() {
    int i = blockIdx.x * blockDim.x + threadIdx.x;
    if (i < NN) {
        g_oisq[i] = rsqrtf((float)g_outdeg[i]);
        g_iisq[i] = rsqrtf((float)g_indeg[i]);
    }
}
__global__ void k_scan1() {
    __shared__ int sh[256];
    int tid = threadIdx.x;
    int idx = blockIdx.x * 256 + tid;
    int v = (idx < NN) ? (g_indeg[idx] - 1) : 0;
    sh[tid] = v; __syncthreads();
    for (int ofs = 1; ofs < 256; ofs <<= 1) {
        int t = (tid >= ofs) ? sh[tid - ofs] : 0;
        __syncthreads(); sh[tid] += t; __syncthreads();
    }
    if (idx < NN) g_off[idx] = sh[tid] - v;
    if (tid == 255) g_bsum[blockIdx.x] = sh[255];
}
__global__ void k_scan2() {
    __shared__ int sh[256];
    int tid = threadIdx.x;
    int v = (tid < SCAN_NB) ? g_bsum[tid] : 0;
    sh[tid] = v; __syncthreads();
    for (int ofs = 1; ofs < 256; ofs <<= 1) {
        int t = (tid >= ofs) ? sh[tid - ofs] : 0;
        __syncthreads(); sh[tid] += t; __syncthreads();
    }
    g_bbase[tid] = sh[tid] - v;
}
__global__ void k_scan3() {
    int idx = blockIdx.x * 256 + threadIdx.x;
    if (idx < NN) g_off[idx] += g_bbase[blockIdx.x];
}
__global__ void k_fill(const int* __restrict__ ei) {
    int e = blockIdx.x * blockDim.x + threadIdx.x;
    if (e < NE) {
        int s = ei[e];
        int d = ei[NE + e];
        int p = g_off[d] + atomicAdd(&g_cur[d], 1);
        g_adj[p] = s;
    }
}

// =============== aggregation (warp/node, F=128, optional bias) ===========
__device__ __forceinline__ void agg128(const float* __restrict__ X,
                                       float* __restrict__ Out,
                                       const float* __restrict__ bias) {
    int w    = (blockIdx.x * blockDim.x + threadIdx.x) >> 5;
    int lane = threadIdx.x & 31;
    if (w >= NN) return;
    float so = g_oisq[w];
    const float4* xr = (const float4*)(X + (size_t)w * 128);
    float4 t = __ldg(&xr[lane]);
    float4 acc = make_float4(t.x * so, t.y * so, t.z * so, t.w * so);
    int j0 = g_off[w], j1 = g_off[w + 1];
    for (int j = j0; j < j1; ++j) {
        int u = g_adj[j];
        float su = g_oisq[u];
        float4 v = __ldg(&((const float4*)(X + (size_t)u * 128))[lane]);
        acc.x += v.x * su; acc.y += v.y * su;
        acc.z += v.z * su; acc.w += v.w * su;
    }
    float si = g_iisq[w];
    float4 o = make_float4(acc.x * si, acc.y * si, acc.z * si, acc.w * si);
    if (bias) {
        float4 b = __ldg(&((const float4*)bias)[lane]);
        o.x += b.x; o.y += b.y; o.z += b.z; o.w += b.w;
    }
    ((float4*)(Out + (size_t)w * 128))[lane] = o;
}

__global__ void agg1_entry(const float* __restrict__ X) { agg128(X, g_m1, nullptr); }
__global__ void agg2_entry(float* __restrict__ Out, const float* __restrict__ b2) {
    agg128(g_m2, Out, b2);
}

// =============== HMMA bf16 hi/lo split GEMM ==============================
// C[M,NTOT] = A[M,K] @ B[K,NTOT] (+bias, relu). CTA tile 128x128, 8 warps,
// warp tile 32x64. K staged in chunks of KC=128 through smem as bf16 hi/lo.
#define KC 128
#define KP (KC + 8)                       // padded stride (bf16 elems)
#define ABYTES (128 * KP * 2)             // 34816
#define BBYTES (128 * KP * 2)             // 34816 (BN=128 rows of B^T)
#define GSMEM  (2 * ABYTES + 2 * BBYTES)  // 139264

template <int K, int NTOT, bool RELU>
__device__ __forceinline__ void gemm_core(const float* __restrict__ A,
                                          const float* __restrict__ B,
                                          const float* __restrict__ bias,
                                          float* __restrict__ C, int M) {
    extern __shared__ char smem[];
    const int OFF_AH = 0, OFF_AL = ABYTES, OFF_BH = 2 * ABYTES, OFF_BL = 2 * ABYTES + BBYTES;
    const int tid  = threadIdx.x;
    const int wid  = tid >> 5;
    const int lane = tid & 31;
    const int mBase = blockIdx.y * 128;
    const int nTile = blockIdx.x * 128;
    const int m0 = (wid >> 1) * 32;       // warp row in tile
    const int n0 = (wid & 1) * 64;        // warp col in tile
    uint32_t sb = s2u(smem);

    float acc[16][4];                     // 2 mfrag x 8 nfrag
#pragma unroll
    for (int i = 0; i < 16; i++)
#pragma unroll
        for (int j = 0; j < 4; j++) acc[i][j] = 0.f;

    for (int kBase = 0; kBase < K; kBase += KC) {
        if (kBase) __syncthreads();
        // ---- fill A hi/lo (rows mBase..+127, cols kBase..+KC) ----
        for (int idx = tid; idx < 128 * (KC / 4); idx += 256) {
            int r  = idx / (KC / 4);
            int k  = (idx - r * (KC / 4)) * 4;
            int gr = mBase + r;
            float4 v = make_float4(0.f, 0.f, 0.f, 0.f);
            if (gr < M) v = *(const float4*)(A + (size_t)gr * K + kBase + k);
            float hx = __bfloat162float(__float2bfloat16(v.x));
            float hy = __bfloat162float(__float2bfloat16(v.y));
            float hz = __bfloat162float(__float2bfloat16(v.z));
            float hw = __bfloat162float(__float2bfloat16(v.w));
            uint32_t off = (uint32_t)(r * KP + k) * 2;
            *(uint2*)(smem + OFF_AH + off) = make_uint2(pack2(v.x, v.y), pack2(v.z, v.w));
            *(uint2*)(smem + OFF_AL + off) =
                make_uint2(pack2(v.x - hx, v.y - hy), pack2(v.z - hz, v.w - hw));
        }
        // ---- fill B^T hi/lo: BT[n][k] = B[kBase+k][nTile+n] ----
        for (int idx = tid; idx < 128 * KC; idx += 256) {
            int k = idx >> 7;              // 0..KC-1
            int n = idx & 127;
            float v = __ldg(&B[(size_t)(kBase + k) * NTOT + nTile + n]);
            float h = __bfloat162float(__float2bfloat16(v));
            uint32_t off = (uint32_t)(n * KP + k) * 2;
            *(unsigned short*)(smem + OFF_BH + off) =
                __bfloat16_as_ushort(__float2bfloat16(v));
            *(unsigned short*)(smem + OFF_BL + off) =
                __bfloat16_as_ushort(__float2bfloat16(v - h));
        }
        __syncthreads();

        // ---- compute over this K chunk ----
        // ldmatrix address helpers
        int arow = (lane & 15);
        int acol = (lane >> 4) << 3;
        int brow = (lane & 7);
        int bcol = ((lane >> 3) & 1) << 3;

#pragma unroll
        for (int ks = 0; ks < KC / 16; ++ks) {
            int k16 = ks * 16;
            uint32_t ah[2][4], al[2][4], bh[8][2], bl[8][2];
#pragma unroll
            for (int mi = 0; mi < 2; mi++) {
                uint32_t ad = sb + OFF_AH
                            + (uint32_t)((m0 + mi * 16 + arow) * KP + k16 + acol) * 2;
                ldm_x4(ah[mi], ad);
                ldm_x4(al[mi], ad + (uint32_t)(OFF_AL - OFF_AH));
            }
#pragma unroll
            for (int ni = 0; ni < 8; ni++) {
                uint32_t bd = sb + OFF_BH
                            + (uint32_t)((n0 + ni * 8 + brow) * KP + k16 + bcol) * 2;
                ldm_x2(bh[ni], bd);
                ldm_x2(bl[ni], bd + (uint32_t)(OFF_BL - OFF_BH));
            }
#pragma unroll
            for (int mi = 0; mi < 2; mi++)
#pragma unroll
                for (int ni = 0; ni < 8; ni++) {
                    float* d = acc[mi * 8 + ni];
                    mma_bf16(d, ah[mi], bh[ni]);   // Ah*Bh
                    mma_bf16(d, ah[mi], bl[ni]);   // Ah*Bl
                    mma_bf16(d, al[mi], bh[ni]);   // Al*Bh
                }
        }
    }

    // ---- epilogue ----
#pragma unroll
    for (int mi = 0; mi < 2; mi++) {
        int row = mBase + m0 + mi * 16 + (lane >> 2);
#pragma unroll
        for (int ni = 0; ni < 8; ni++) {
            int col = nTile + n0 + ni * 8 + 2 * (lane & 3);
            float* d = acc[mi * 8 + ni];
            float bx = 0.f, by = 0.f;
            if (RELU) { bx = __ldg(&bias[col]); by = __ldg(&bias[col + 1]); }
            if (row < M) {
                float2 o = make_float2(d[0] + bx, d[1] + by);
                if (RELU) { o.x = fmaxf(o.x, 0.f); o.y = fmaxf(o.y, 0.f); }
                *(float2*)(C + (size_t)row * NTOT + col) = o;
            }
            if (row + 8 < M) {
                float2 o = make_float2(d[2] + bx, d[3] + by);
                if (RELU) { o.x = fmaxf(o.x, 0.f); o.y = fmaxf(o.y, 0.f); }
                *(float2*)(C + (size_t)(row + 8) * NTOT + col) = o;
            }
        }
    }
}

// layer 1: g_h1 = relu(g_m1 @ W1 + b1)   M=NN K=128 NTOT=256
__global__ void __launch_bounds__(256, 1)
gemm1_tc(const float* __restrict__ W1, const float* __restrict__ b1) {
    gemm_core<128, 256, true>(g_m1, W1, b1, g_h1, NN);
}
// layer 2: g_m2 = g_h1 @ W2               M=NN K=256 NTOT=128
__global__ void __launch_bounds__(256, 1)
gemm2_tc(const float* __restrict__ W2) {
    gemm_core<256, 128, false>(g_h1, W2, nullptr, g_m2, NN);
}

// ======================= launcher ========================================
extern "C" void kernel_launch(void* const* d_in, const int* in_sizes, int n_in,
                              void* d_out, int out_size) {
    const float* x  = (const float*)d_in[0];
    const int*   ei = (const int*)d_in[1];
    const float* W1 = (const float*)d_in[2];
    const float* b1 = (const float*)d_in[3];
    const float* W2 = (const float*)d_in[4];
    const float* b2 = (const float*)d_in[5];
    float* out = (float*)d_out;

    cudaFuncSetAttribute(gemm1_tc, cudaFuncAttributeMaxDynamicSharedMemorySize, GSMEM);
    cudaFuncSetAttribute(gemm2_tc, cudaFuncAttributeMaxDynamicSharedMemorySize, GSMEM);

    const int TB = 256;
    int gN = (NN + TB - 1) / TB;
    int gE = (NE + TB - 1) / TB;

    k_init<<<gN, TB>>>();
    k_count<<<gE, TB>>>(ei);
    k_isqrt<<<gN, TB>>>();
    k_scan1<<<SCAN_NB, 256>>>();
    k_scan2<<<1, 256>>>();
    k_scan3<<<SCAN_NB, 256>>>();
    k_fill<<<gE, TB>>>(ei);

    int aggBlocks = (NN * 32 + TB - 1) / TB;
    agg1_entry<<<aggBlocks, TB>>>(x);

    const int MT = (NN + 127) / 128;   // 391
    gemm1_tc<<<dim3(2, MT), 256, GSMEM>>>(W1, b1);   // N=256 -> 2 tiles
    gemm2_tc<<<dim3(1, MT), 256, GSMEM>>>(W2);       // N=128 -> 1 tile

    agg2_entry<<<aggBlocks, TB>>>(out, b2);
}

// round 11
// speedup vs baseline: 1.8727x; 1.4732x over previous
#include <cuda_runtime.h>
#include <cuda_bf16.h>
#include <cstdint>

#define NN   50000
#define NE   800000
#define FIN  128
#define FHID 256
#define FOUT 128
#define SCAN_NB ((NN + 255) / 256)   // 196

// -------- scratch ---------------------------------------------------------
__device__ int   g_outdeg[NN];
__device__ int   g_indeg[NN];
__device__ int   g_cur[NN];
__device__ int   g_off[NN + 1];
__device__ int   g_adj[NE];
__device__ int   g_bsum[256];
__device__ int   g_bbase[256];
__device__ float g_oisq[NN];
__device__ float g_iisq[NN];

// bf16 hi/lo operand storage
__device__ __nv_bfloat16 g_m1h[(size_t)NN * FIN];
__device__ __nv_bfloat16 g_m1l[(size_t)NN * FIN];
__device__ __nv_bfloat16 g_h1h[(size_t)NN * FHID];
__device__ __nv_bfloat16 g_h1l[(size_t)NN * FHID];
__device__ __nv_bfloat16 g_w1hT[(size_t)FHID * FIN];   // [n][k] n-major
__device__ __nv_bfloat16 g_w1lT[(size_t)FHID * FIN];
__device__ __nv_bfloat16 g_w2hT[(size_t)FOUT * FHID];
__device__ __nv_bfloat16 g_w2lT[(size_t)FOUT * FHID];
__device__ float g_m2[(size_t)NN * FOUT];              // h1@W2 fp32

// ======================= helpers =========================================
__device__ __forceinline__ uint32_t s2u(const void* p) {
    uint32_t a;
    asm("{ .reg .u64 t; cvta.to.shared.u64 t, %1; cvt.u32.u64 %0, t; }"
        : "=r"(a) : "l"(p));
    return a;
}
__device__ __forceinline__ void ldm_x4(uint32_t* r, uint32_t addr) {
    asm volatile("ldmatrix.sync.aligned.m8n8.x4.shared.b16 {%0,%1,%2,%3}, [%4];"
                 : "=r"(r[0]), "=r"(r[1]), "=r"(r[2]), "=r"(r[3]) : "r"(addr));
}
__device__ __forceinline__ void ldm_x2(uint32_t* r, uint32_t addr) {
    asm volatile("ldmatrix.sync.aligned.m8n8.x2.shared.b16 {%0,%1}, [%2];"
                 : "=r"(r[0]), "=r"(r[1]) : "r"(addr));
}
__device__ __forceinline__ void mma_bf16(float* d, const uint32_t* a, const uint32_t* b) {
    asm volatile(
        "mma.sync.aligned.m16n8k16.row.col.f32.bf16.bf16.f32 "
        "{%0,%1,%2,%3}, {%4,%5,%6,%7}, {%8,%9}, {%0,%1,%2,%3};"
        : "+f"(d[0]), "+f"(d[1]), "+f"(d[2]), "+f"(d[3])
        : "r"(a[0]), "r"(a[1]), "r"(a[2]), "r"(a[3]), "r"(b[0]), "r"(b[1]));
}
__device__ __forceinline__ void cpa16(uint32_t dst, const void* src, bool pred) {
    int sz = pred ? 16 : 0;
    asm volatile("cp.async.cg.shared.global [%0], [%1], 16, %2;"
                 :: "r"(dst), "l"(src), "r"(sz));
}
__device__ __forceinline__ uint32_t pack2(float a, float b) {
    unsigned short ha = __bfloat16_as_ushort(__float2bfloat16(a));
    unsigned short hb = __bfloat16_as_ushort(__float2bfloat16(b));
    return (uint32_t)ha | ((uint32_t)hb << 16);
}

// ======================= setup kernels ===================================
__global__ void k_init() {
    int i = blockIdx.x * blockDim.x + threadIdx.x;
    if (i < NN) { g_outdeg[i] = 1; g_indeg[i] = 1; g_cur[i] = 0; }
    if (i == 0) g_off[NN] = NE;
}
__global__ void k_count(const int* __restrict__ ei) {
    int e = blockIdx.x * blockDim.x + threadIdx.x;
    if (e < NE) {
        atomicAdd(&g_outdeg[ei[e]], 1);
        atomicAdd(&g_indeg[ei[NE + e]], 1);
    }
}
__global__ void k_isqrt() {
    int i = blockIdx.x * blockDim.x + threadIdx.x;
    if (i < NN) {
        g_oisq[i] = rsqrtf((float)g_outdeg[i]);
        g_iisq[i] = rsqrtf((float)g_indeg[i]);
    }
}
__global__ void k_scan1() {
    __shared__ int sh[256];
    int tid = threadIdx.x;
    int idx = blockIdx.x * 256 + tid;
    int v = (idx < NN) ? (g_indeg[idx] - 1) : 0;
    sh[tid] = v; __syncthreads();
    for (int ofs = 1; ofs < 256; ofs <<= 1) {
        int t = (tid >= ofs) ? sh[tid - ofs] : 0;
        __syncthreads(); sh[tid] += t; __syncthreads();
    }
    if (idx < NN) g_off[idx] = sh[tid] - v;
    if (tid == 255) g_bsum[blockIdx.x] = sh[255];
}
__global__ void k_scan2() {
    __shared__ int sh[256];
    int tid = threadIdx.x;
    int v = (tid < SCAN_NB) ? g_bsum[tid] : 0;
    sh[tid] = v; __syncthreads();
    for (int ofs = 1; ofs < 256; ofs <<= 1) {
        int t = (tid >= ofs) ? sh[tid - ofs] : 0;
        __syncthreads(); sh[tid] += t; __syncthreads();
    }
    g_bbase[tid] = sh[tid] - v;
}
__global__ void k_scan3() {
    int idx = blockIdx.x * 256 + threadIdx.x;
    if (idx < NN) g_off[idx] += g_bbase[blockIdx.x];
}
__global__ void k_fill(const int* __restrict__ ei) {
    int e = blockIdx.x * blockDim.x + threadIdx.x;
    if (e < NE) {
        int s = ei[e];
        int d = ei[NE + e];
        int p = g_off[d] + atomicAdd(&g_cur[d], 1);
        g_adj[p] = s;
    }
}
// weight split + transpose: WhT[n][k] = bf16hi(W[k][n]), WlT = residual
__global__ void k_split1(const float* __restrict__ W1) {
    int i = blockIdx.x * blockDim.x + threadIdx.x;   // over FIN*FHID
    if (i < FIN * FHID) {
        int k = i / FHID, n = i - k * FHID;
        float v = W1[i];
        __nv_bfloat16 h = __float2bfloat16(v);
        g_w1hT[(size_t)n * FIN + k] = h;
        g_w1lT[(size_t)n * FIN + k] = __float2bfloat16(v - __bfloat162float(h));
    }
}
__global__ void k_split2(const float* __restrict__ W2) {
    int i = blockIdx.x * blockDim.x + threadIdx.x;   // over FHID*FOUT
    if (i < FHID * FOUT) {
        int k = i / FOUT, n = i - k * FOUT;
        float v = W2[i];
        __nv_bfloat16 h = __float2bfloat16(v);
        g_w2hT[(size_t)n * FHID + k] = h;
        g_w2lT[(size_t)n * FHID + k] = __float2bfloat16(v - __bfloat162float(h));
    }
}

// =============== aggregation (warp/node, F=128) ==========================
// agg1: reads x fp32, writes m1h/m1l split bf16
__global__ void agg1_entry(const float* __restrict__ X) {
    int w    = (blockIdx.x * blockDim.x + threadIdx.x) >> 5;
    int lane = threadIdx.x & 31;
    if (w >= NN) return;
    float so = g_oisq[w];
    float4 t = __ldg(&((const float4*)(X + (size_t)w * 128))[lane]);
    float4 acc = make_float4(t.x * so, t.y * so, t.z * so, t.w * so);
    int j0 = g_off[w], j1 = g_off[w + 1];
    for (int j = j0; j < j1; ++j) {
        int u = g_adj[j];
        float su = g_oisq[u];
        float4 v = __ldg(&((const float4*)(X + (size_t)u * 128))[lane]);
        acc.x += v.x * su; acc.y += v.y * su;
        acc.z += v.z * su; acc.w += v.w * su;
    }
    float si = g_iisq[w];
    float o[4] = { acc.x * si, acc.y * si, acc.z * si, acc.w * si };
    float h[4];
#pragma unroll
    for (int i = 0; i < 4; i++) h[i] = __bfloat162float(__float2bfloat16(o[i]));
    size_t base = ((size_t)w * 128 + lane * 4);
    *(uint2*)(g_m1h + base) = make_uint2(pack2(o[0], o[1]), pack2(o[2], o[3]));
    *(uint2*)(g_m1l + base) =
        make_uint2(pack2(o[0] - h[0], o[1] - h[1]), pack2(o[2] - h[2], o[3] - h[3]));
}
// agg2: reads g_m2 fp32, adds b2, writes out fp32
__global__ void agg2_entry(float* __restrict__ Out, const float* __restrict__ b2) {
    int w    = (blockIdx.x * blockDim.x + threadIdx.x) >> 5;
    int lane = threadIdx.x & 31;
    if (w >= NN) return;
    const float* X = g_m2;
    float so = g_oisq[w];
    float4 t = __ldg(&((const float4*)(X + (size_t)w * 128))[lane]);
    float4 acc = make_float4(t.x * so, t.y * so, t.z * so, t.w * so);
    int j0 = g_off[w], j1 = g_off[w + 1];
    for (int j = j0; j < j1; ++j) {
        int u = g_adj[j];
        float su = g_oisq[u];
        float4 v = __ldg(&((const float4*)(X + (size_t)u * 128))[lane]);
        acc.x += v.x * su; acc.y += v.y * su;
        acc.z += v.z * su; acc.w += v.w * su;
    }
    float si = g_iisq[w];
    float4 b = __ldg(&((const float4*)b2)[lane]);
    float4 o = make_float4(acc.x * si + b.x, acc.y * si + b.y,
                           acc.z * si + b.z, acc.w * si + b.w);
    ((float4*)(Out + (size_t)w * 128))[lane] = o;
}

// =============== HMMA bf16 hi/lo GEMM (pre-split operands) ===============
// CTA 128x128, 8 warps (32x64), K chunks of 64, XOR-swizzled smem,
// cp.async fills, occupancy 2.
#define CHUNK 64
#define MAT_BYTES (128 * 128)          // 128 rows x 64 bf16 = 128B/row
#define GSMEM (4 * MAT_BYTES)          // 64 KB

template <int K, int NOUT, bool SPLIT_OUT>
__device__ __forceinline__ void gemm_core(
    const __nv_bfloat16* __restrict__ Ah, const __nv_bfloat16* __restrict__ Al,
    const __nv_bfloat16* __restrict__ BhT, const __nv_bfloat16* __restrict__ BlT,
    const float* __restrict__ bias,
    float* __restrict__ Cf, __nv_bfloat16* __restrict__ Chh,
    __nv_bfloat16* __restrict__ Chl, int M) {
    extern __shared__ char smem[];
    const int OFF_AH = 0, OFF_AL = MAT_BYTES, OFF_BH = 2 * MAT_BYTES, OFF_BL = 3 * MAT_BYTES;
    const int tid  = threadIdx.x;
    const int wid  = tid >> 5;
    const int lane = tid & 31;
    const int mBase = blockIdx.y * 128;
    const int nTile = blockIdx.x * 128;
    const int m0 = (wid >> 1) * 32;
    const int n0 = (wid & 1) * 64;
    uint32_t sb = s2u(smem);

    float acc[16][4];
#pragma unroll
    for (int i = 0; i < 16; i++)
#pragma unroll
        for (int j = 0; j < 4; j++) acc[i][j] = 0.f;

    for (int kc = 0; kc < K / CHUNK; ++kc) {
        const int kBase = kc * CHUNK;
        if (kc) __syncthreads();
        // ---- cp.async fill: 1024 16B-chunks per matrix ----
#pragma unroll
        for (int it4 = 0; it4 < 4; ++it4) {
            int item = it4 * 256 + tid;
            int r = item >> 3, c = item & 7;
            uint32_t d = sb + (uint32_t)(r << 7) + ((uint32_t)(c ^ (r & 7)) << 4);
            int gr = mBase + r;
            bool ok = gr < M;
            int gre = ok ? gr : 0;
            size_t aoff = (size_t)gre * K + kBase + c * 8;
            cpa16(d + OFF_AH, Ah + aoff, ok);
            cpa16(d + OFF_AL, Al + aoff, ok);
            size_t boff = (size_t)(nTile + r) * K + kBase + c * 8;
            cpa16(d + OFF_BH, BhT + boff, true);
            cpa16(d + OFF_BL, BlT + boff, true);
        }
        asm volatile("cp.async.commit_group;");
        asm volatile("cp.async.wait_group 0;");
        __syncthreads();

        // ---- compute: 4 k16 steps ----
#pragma unroll
        for (int ks = 0; ks < CHUNK / 16; ++ks) {
            uint32_t ah[2][4], al[2][4];
#pragma unroll
            for (int mi = 0; mi < 2; mi++) {
                int ra = m0 + mi * 16 + (lane & 15);
                int ca = 2 * ks + (lane >> 4);
                uint32_t ad = sb + (uint32_t)(ra << 7)
                            + ((uint32_t)(ca ^ (ra & 7)) << 4);
                ldm_x4(ah[mi], ad + OFF_AH);
                ldm_x4(al[mi], ad + OFF_AL);
            }
#pragma unroll
            for (int half = 0; half < 2; ++half) {
                uint32_t bh[4][2], bl[4][2];
#pragma unroll
                for (int q = 0; q < 4; q++) {
                    int rn = n0 + (half * 4 + q) * 8 + (lane & 7);
                    int cb = 2 * ks + ((lane >> 3) & 1);
                    uint32_t bd = sb + (uint32_t)(rn << 7)
                                + ((uint32_t)(cb ^ (rn & 7)) << 4);
                    ldm_x2(bh[q], bd + OFF_BH);
                    ldm_x2(bl[q], bd + OFF_BL);
                }
#pragma unroll
                for (int mi = 0; mi < 2; mi++)
#pragma unroll
                    for (int q = 0; q < 4; q++) {
                        float* d = acc[mi * 8 + half * 4 + q];
                        mma_bf16(d, ah[mi], bh[q]);
                        mma_bf16(d, ah[mi], bl[q]);
                        mma_bf16(d, al[mi], bh[q]);
                    }
            }
        }
    }

    // ---- epilogue ----
#pragma unroll
    for (int mi = 0; mi < 2; mi++) {
        int row0 = mBase + m0 + mi * 16 + (lane >> 2);
#pragma unroll
        for (int ni = 0; ni < 8; ni++) {
            int col = nTile + n0 + ni * 8 + 2 * (lane & 3);
            float* d = acc[mi * 8 + ni];
#pragma unroll
            for (int hh = 0; hh < 2; hh++) {
                int row = row0 + hh * 8;
                if (row >= M) continue;
                float v0 = d[hh * 2 + 0], v1 = d[hh * 2 + 1];
                if (SPLIT_OUT) {
                    v0 = fmaxf(v0 + __ldg(&bias[col]), 0.f);
                    v1 = fmaxf(v1 + __ldg(&bias[col + 1]), 0.f);
                    float h0 = __bfloat162float(__float2bfloat16(v0));
                    float h1 = __bfloat162float(__float2bfloat16(v1));
                    size_t o = (size_t)row * NOUT + col;
                    *(uint32_t*)(Chh + o) = pack2(v0, v1);
                    *(uint32_t*)(Chl + o) = pack2(v0 - h0, v1 - h1);
                } else {
                    *(float2*)(Cf + (size_t)row * NOUT + col) = make_float2(v0, v1);
                }
            }
        }
    }
}

__global__ void __launch_bounds__(256, 2)
gemm1_tc(const float* __restrict__ b1) {
    gemm_core<128, 256, true>(g_m1h, g_m1l, g_w1hT, g_w1lT, b1,
                              nullptr, g_h1h, g_h1l, NN);
}
__global__ void __launch_bounds__(256, 2)
gemm2_tc() {
    gemm_core<256, 128, false>(g_h1h, g_h1l, g_w2hT, g_w2lT, nullptr,
                               g_m2, nullptr, nullptr, NN);
}

// ======================= launcher ========================================
extern "C" void kernel_launch(void* const* d_in, const int* in_sizes, int n_in,
                              void* d_out, int out_size) {
    const float* x  = (const float*)d_in[0];
    const int*   ei = (const int*)d_in[1];
    const float* W1 = (const float*)d_in[2];
    const float* b1 = (const float*)d_in[3];
    const float* W2 = (const float*)d_in[4];
    const float* b2 = (const float*)d_in[5];
    float* out = (float*)d_out;

    cudaFuncSetAttribute(gemm1_tc, cudaFuncAttributeMaxDynamicSharedMemorySize, GSMEM);
    cudaFuncSetAttribute(gemm2_tc, cudaFuncAttributeMaxDynamicSharedMemorySize, GSMEM);

    const int TB = 256;
    int gN = (NN + TB - 1) / TB;
    int gE = (NE + TB - 1) / TB;

    k_init<<<gN, TB>>>();
    k_count<<<gE, TB>>>(ei);
    k_isqrt<<<gN, TB>>>();
    k_scan1<<<SCAN_NB, 256>>>();
    k_scan2<<<1, 256>>>();
    k_scan3<<<SCAN_NB, 256>>>();
    k_fill<<<gE, TB>>>(ei);
    k_split1<<<(FIN * FHID + TB - 1) / TB, TB>>>(W1);
    k_split2<<<(FHID * FOUT + TB - 1) / TB, TB>>>(W2);

    int aggBlocks = (NN * 32 + TB - 1) / TB;
    agg1_entry<<<aggBlocks, TB>>>(x);

    const int MT = (NN + 127) / 128;   // 391
    gemm1_tc<<<dim3(2, MT), 256, GSMEM>>>(b1);
    gemm2_tc<<<dim3(1, MT), 256, GSMEM>>>();

    agg2_entry<<<aggBlocks, TB>>>(out, b2);
}

// round 16
// speedup vs baseline: 2.4784x; 1.3234x over previous
#include <cuda_runtime.h>
#include <cuda_fp16.h>
#include <cstdint>

#define NN   50000
#define NE   800000
#define FIN  128
#define FHID 256
#define FOUT 128
#define SCAN_NB ((NN + 255) / 256)   // 196

// -------- scratch ---------------------------------------------------------
__device__ int   g_outdeg[NN];
__device__ int   g_indeg[NN];
__device__ int   g_cur[NN];
__device__ int   g_off[NN + 1];
__device__ int   g_adj[NE];
__device__ int   g_bsum[256];
__device__ int   g_bbase[256];
__device__ float g_oisq[NN];
__device__ float g_iisq[NN];

// fp16 operand storage
__device__ __half g_m1h[(size_t)NN * FIN];
__device__ __half g_h1h[(size_t)NN * FHID];
__device__ __half g_w1hT[(size_t)FHID * FIN];   // [n][k] n-major
__device__ __half g_w2hT[(size_t)FOUT * FHID];
__device__ float  g_m2[(size_t)NN * FOUT];      // h1@W2 fp32

// ======================= helpers =========================================
__device__ __forceinline__ uint32_t s2u(const void* p) {
    uint32_t a;
    asm("{ .reg .u64 t; cvta.to.shared.u64 t, %1; cvt.u32.u64 %0, t; }"
        : "=r"(a) : "l"(p));
    return a;
}
__device__ __forceinline__ void ldm_x4(uint32_t* r, uint32_t addr) {
    asm volatile("ldmatrix.sync.aligned.m8n8.x4.shared.b16 {%0,%1,%2,%3}, [%4];"
                 : "=r"(r[0]), "=r"(r[1]), "=r"(r[2]), "=r"(r[3]) : "r"(addr));
}
__device__ __forceinline__ void ldm_x2(uint32_t* r, uint32_t addr) {
    asm volatile("ldmatrix.sync.aligned.m8n8.x2.shared.b16 {%0,%1}, [%2];"
                 : "=r"(r[0]), "=r"(r[1]) : "r"(addr));
}
__device__ __forceinline__ void mma_f16(float* d, const uint32_t* a, const uint32_t* b) {
    asm volatile(
        "mma.sync.aligned.m16n8k16.row.col.f32.f16.f16.f32 "
        "{%0,%1,%2,%3}, {%4,%5,%6,%7}, {%8,%9}, {%0,%1,%2,%3};"
        : "+f"(d[0]), "+f"(d[1]), "+f"(d[2]), "+f"(d[3])
        : "r"(a[0]), "r"(a[1]), "r"(a[2]), "r"(a[3]), "r"(b[0]), "r"(b[1]));
}
__device__ __forceinline__ void cpa16(uint32_t dst, const void* src, bool pred) {
    int sz = pred ? 16 : 0;
    asm volatile("cp.async.cg.shared.global [%0], [%1], 16, %2;"
                 :: "r"(dst), "l"(src), "r"(sz));
}
__device__ __forceinline__ uint32_t pack2h(float a, float b) {
    __half2 h = __floats2half2_rn(a, b);
    return *(uint32_t*)&h;
}

// ======================= setup kernels ===================================
__global__ void k_init() {
    int i = blockIdx.x * blockDim.x + threadIdx.x;
    if (i < NN) { g_outdeg[i] = 1; g_indeg[i] = 1; g_cur[i] = 0; }
    if (i == 0) g_off[NN] = NE;
}
__global__ void k_count(const int* __restrict__ ei) {
    int e = blockIdx.x * blockDim.x + threadIdx.x;
    if (e < NE) {
        atomicAdd(&g_outdeg[ei[e]], 1);
        atomicAdd(&g_indeg[ei[NE + e]], 1);
    }
}
__global__ void k_scan1() {
    __shared__ int sh[256];
    int tid = threadIdx.x;
    int idx = blockIdx.x * 256 + tid;
    int v = (idx < NN) ? (g_indeg[idx] - 1) : 0;
    sh[tid] = v; __syncthreads();
    for (int ofs = 1; ofs < 256; ofs <<= 1) {
        int t = (tid >= ofs) ? sh[tid - ofs] : 0;
        __syncthreads(); sh[tid] += t; __syncthreads();
    }
    if (idx < NN) g_off[idx] = sh[tid] - v;
    if (tid == 255) g_bsum[blockIdx.x] = sh[255];
}
__global__ void k_scan2() {
    __shared__ int sh[256];
    int tid = threadIdx.x;
    int v = (tid < SCAN_NB) ? g_bsum[tid] : 0;
    sh[tid] = v; __syncthreads();
    for (int ofs = 1; ofs < 256; ofs <<= 1) {
        int t = (tid >= ofs) ? sh[tid - ofs] : 0;
        __syncthreads(); sh[tid] += t; __syncthreads();
    }
    g_bbase[tid] = sh[tid] - v;
}
// scan3 + isqrt fused (both elementwise over nodes, both post-count)
__global__ void k_scan3() {
    int idx = blockIdx.x * 256 + threadIdx.x;
    if (idx < NN) {
        g_off[idx] += g_bbase[blockIdx.x];
        g_oisq[idx] = rsqrtf((float)g_outdeg[idx]);
        g_iisq[idx] = rsqrtf((float)g_indeg[idx]);
    }
}
__global__ void k_fill(const int* __restrict__ ei) {
    int e = blockIdx.x * blockDim.x + threadIdx.x;
    if (e < NE) {
        int s = ei[e];
        int d = ei[NE + e];
        int p = g_off[d] + atomicAdd(&g_cur[d], 1);
        g_adj[p] = s;
    }
}
// fused weight transpose to fp16 (both weight matrices are 32768 elements)
__global__ void k_split(const float* __restrict__ W1, const float* __restrict__ W2) {
    int i = blockIdx.x * blockDim.x + threadIdx.x;
    if (i < FIN * FHID) {
        int k = i / FHID, n = i - k * FHID;
        g_w1hT[(size_t)n * FIN + k] = __float2half(W1[i]);
    }
    if (i < FHID * FOUT) {
        int k = i / FOUT, n = i - k * FOUT;
        g_w2hT[(size_t)n * FHID + k] = __float2half(W2[i]);
    }
}

// =============== aggregation (warp/node, F=128) ==========================
// agg1: reads x fp32, writes m1 fp16
__global__ void agg1_entry(const float* __restrict__ X) {
    int w    = (blockIdx.x * blockDim.x + threadIdx.x) >> 5;
    int lane = threadIdx.x & 31;
    if (w >= NN) return;
    float so = g_oisq[w];
    float4 t = __ldg(&((const float4*)(X + (size_t)w * 128))[lane]);
    float4 acc = make_float4(t.x * so, t.y * so, t.z * so, t.w * so);
    int j0 = g_off[w], j1 = g_off[w + 1];
    for (int j = j0; j < j1; ++j) {
        int u = g_adj[j];
        float su = g_oisq[u];
        float4 v = __ldg(&((const float4*)(X + (size_t)u * 128))[lane]);
        acc.x += v.x * su; acc.y += v.y * su;
        acc.z += v.z * su; acc.w += v.w * su;
    }
    float si = g_iisq[w];
    size_t base = ((size_t)w * 128 + lane * 4);
    *(uint2*)(g_m1h + base) =
        make_uint2(pack2h(acc.x * si, acc.y * si), pack2h(acc.z * si, acc.w * si));
}
// agg2: reads g_m2 fp32, adds b2, writes out fp32
__global__ void agg2_entry(float* __restrict__ Out, const float* __restrict__ b2) {
    int w    = (blockIdx.x * blockDim.x + threadIdx.x) >> 5;
    int lane = threadIdx.x & 31;
    if (w >= NN) return;
    const float* X = g_m2;
    float so = g_oisq[w];
    float4 t = __ldg(&((const float4*)(X + (size_t)w * 128))[lane]);
    float4 acc = make_float4(t.x * so, t.y * so, t.z * so, t.w * so);
    int j0 = g_off[w], j1 = g_off[w + 1];
    for (int j = j0; j < j1; ++j) {
        int u = g_adj[j];
        float su = g_oisq[u];
        float4 v = __ldg(&((const float4*)(X + (size_t)u * 128))[lane]);
        acc.x += v.x * su; acc.y += v.y * su;
        acc.z += v.z * su; acc.w += v.w * su;
    }
    float si = g_iisq[w];
    float4 b = __ldg(&((const float4*)b2)[lane]);
    float4 o = make_float4(acc.x * si + b.x, acc.y * si + b.y,
                           acc.z * si + b.z, acc.w * si + b.w);
    ((float4*)(Out + (size_t)w * 128))[lane] = o;
}

// =============== HMMA fp16 single-pass GEMM ==============================
// CTA 128x128, 8 warps (32x64), K chunks of 64, XOR-swizzled smem,
// cp.async fills, 32KB smem, occupancy 2 (reg-limited).
#define CHUNK 64
#define MAT_BYTES (128 * 128)          // 128 rows x 64 fp16 = 128B/row
#define GSMEM (2 * MAT_BYTES)          // 32 KB

template <int K, int NOUT, bool SPLIT_OUT>
__device__ __forceinline__ void gemm_core(
    const __half* __restrict__ Ah, const __half* __restrict__ BhT,
    const float* __restrict__ bias,
    float* __restrict__ Cf, __half* __restrict__ Ch, int M) {
    extern __shared__ char smem[];
    const int OFF_A = 0, OFF_B = MAT_BYTES;
    const int tid  = threadIdx.x;
    const int wid  = tid >> 5;
    const int lane = tid & 31;
    const int mBase = blockIdx.y * 128;
    const int nTile = blockIdx.x * 128;
    const int m0 = (wid >> 1) * 32;
    const int n0 = (wid & 1) * 64;
    uint32_t sb = s2u(smem);

    float acc[16][4];
#pragma unroll
    for (int i = 0; i < 16; i++)
#pragma unroll
        for (int j = 0; j < 4; j++) acc[i][j] = 0.f;

    for (int kc = 0; kc < K / CHUNK; ++kc) {
        const int kBase = kc * CHUNK;
        if (kc) __syncthreads();
        // ---- cp.async fill: 1024 16B-chunks per matrix ----
#pragma unroll
        for (int it4 = 0; it4 < 4; ++it4) {
            int item = it4 * 256 + tid;
            int r = item >> 3, c = item & 7;
            uint32_t d = sb + (uint32_t)(r << 7) + ((uint32_t)(c ^ (r & 7)) << 4);
            int gr = mBase + r;
            bool ok = gr < M;
            int gre = ok ? gr : 0;
            cpa16(d + OFF_A, Ah + (size_t)gre * K + kBase + c * 8, ok);
            cpa16(d + OFF_B, BhT + (size_t)(nTile + r) * K + kBase + c * 8, true);
        }
        asm volatile("cp.async.commit_group;");
        asm volatile("cp.async.wait_group 0;");
        __syncthreads();

        // ---- compute: 4 k16 steps ----
#pragma unroll
        for (int ks = 0; ks < CHUNK / 16; ++ks) {
            uint32_t ah[2][4];
#pragma unroll
            for (int mi = 0; mi < 2; mi++) {
                int ra = m0 + mi * 16 + (lane & 15);
                int ca = 2 * ks + (lane >> 4);
                uint32_t ad = sb + (uint32_t)(ra << 7)
                            + ((uint32_t)(ca ^ (ra & 7)) << 4);
                ldm_x4(ah[mi], ad + OFF_A);
            }
#pragma unroll
            for (int half = 0; half < 2; ++half) {
                uint32_t bh[4][2];
#pragma unroll
                for (int q = 0; q < 4; q++) {
                    int rn = n0 + (half * 4 + q) * 8 + (lane & 7);
                    int cb = 2 * ks + ((lane >> 3) & 1);
                    uint32_t bd = sb + (uint32_t)(rn << 7)
                                + ((uint32_t)(cb ^ (rn & 7)) << 4);
                    ldm_x2(bh[q], bd + OFF_B);
                }
#pragma unroll
                for (int mi = 0; mi < 2; mi++)
#pragma unroll
                    for (int q = 0; q < 4; q++)
                        mma_f16(acc[mi * 8 + half * 4 + q], ah[mi], bh[q]);
            }
        }
    }

    // ---- epilogue ----
#pragma unroll
    for (int mi = 0; mi < 2; mi++) {
        int row0 = mBase + m0 + mi * 16 + (lane >> 2);
#pragma unroll
        for (int ni = 0; ni < 8; ni++) {
            int col = nTile + n0 + ni * 8 + 2 * (lane & 3);
            float* d = acc[mi * 8 + ni];
#pragma unroll
            for (int hh = 0; hh < 2; hh++) {
                int row = row0 + hh * 8;
                if (row >= M) continue;
                float v0 = d[hh * 2 + 0], v1 = d[hh * 2 + 1];
                if (SPLIT_OUT) {
                    v0 = fmaxf(v0 + __ldg(&bias[col]), 0.f);
                    v1 = fmaxf(v1 + __ldg(&bias[col + 1]), 0.f);
                    *(uint32_t*)(Ch + (size_t)row * NOUT + col) = pack2h(v0, v1);
                } else {
                    *(float2*)(Cf + (size_t)row * NOUT + col) = make_float2(v0, v1);
                }
            }
        }
    }
}

__global__ void __launch_bounds__(256, 2)
gemm1_tc(const float* __restrict__ b1) {
    gemm_core<128, 256, true>(g_m1h, g_w1hT, b1, nullptr, g_h1h, NN);
}
__global__ void __launch_bounds__(256, 2)
gemm2_tc() {
    gemm_core<256, 128, false>(g_h1h, g_w2hT, nullptr, g_m2, nullptr, NN);
}

// ======================= launcher ========================================
extern "C" void kernel_launch(void* const* d_in, const int* in_sizes, int n_in,
                              void* d_out, int out_size) {
    const float* x  = (const float*)d_in[0];
    const int*   ei = (const int*)d_in[1];
    const float* W1 = (const float*)d_in[2];
    const float* b1 = (const float*)d_in[3];
    const float* W2 = (const float*)d_in[4];
    const float* b2 = (const float*)d_in[5];
    float* out = (float*)d_out;

    cudaFuncSetAttribute(gemm1_tc, cudaFuncAttributeMaxDynamicSharedMemorySize, GSMEM);
    cudaFuncSetAttribute(gemm2_tc, cudaFuncAttributeMaxDynamicSharedMemorySize, GSMEM);

    const int TB = 256;
    int gN = (NN + TB - 1) / TB;
    int gE = (NE + TB - 1) / TB;

    k_init<<<gN, TB>>>();
    k_count<<<gE, TB>>>(ei);
    k_scan1<<<SCAN_NB, 256>>>();
    k_scan2<<<1, 256>>>();
    k_scan3<<<SCAN_NB, 256>>>();
    k_fill<<<gE, TB>>>(ei);
    k_split<<<(FIN * FHID + TB - 1) / TB, TB>>>(W1, W2);

    int aggBlocks = (NN * 32 + TB - 1) / TB;
    agg1_entry<<<aggBlocks, TB>>>(x);

    const int MT = (NN + 127) / 128;   // 391
    gemm1_tc<<<dim3(2, MT), 256, GSMEM>>>(b1);
    gemm2_tc<<<dim3(1, MT), 256, GSMEM>>>();

    agg2_entry<<<aggBlocks, TB>>>(out, b2);
}